// round 14
// baseline (speedup 1.0000x reference)
#include <cuda_runtime.h>
#include <cstdint>

// out[i] = one_hot(argmax_j( b[j] + sum_k x[i,k]*W[k,j] ), 64)
//
// R10: persistent, 1 block/SM, TPB=512 = 4 INDEPENDENT groups of 128 threads
// (4 warps/SMSP). Each group streams 64-row tiles with its own double-buffered
// cp.async pipeline + named barrier. Geometry: g = tl>>4 in [0,8): rows
// 8g..8g+7 ; a = tl&15: cols 4a..4a+3. acc = 8x4 packed f32x2 = 32 regs.
// LDS/FFMA2 = 0.094 (1 W + 0.5 x LDS per k vs 16 FFMA2) so L1 stays moderate
// at 16 warps/SM; the 4th warp/SMSP covers the latency bubbles that capped
// R8/R9 at fma=68%.
// Numerics: per column b-init + ascending-k fp32 fma.rn.f32x2 chain ==
// bit-identical to all passing rounds (rel_err = 1 flipped row, zero margin).

#define DIMS 64
#define TPB 512
#define NG 4               // groups
#define GSZ 128            // threads per group
#define TROWS 64           // rows per tile
#define TILE_F4 (TROWS * DIMS / 4)    // 1024 float4 per tile
#define TILE_FLOATS (TROWS * DIMS)    // 4096 floats

// smem floats: Ws[4096] | bs[64] | xs[8][4096]
#define SMEM_FLOATS (4096 + 64 + 2 * NG * TILE_FLOATS)
#define SMEM_BYTES (SMEM_FLOATS * 4)   // 147,712 B

__device__ __forceinline__ unsigned long long fma2(unsigned long long a,
                                                   unsigned long long b,
                                                   unsigned long long c) {
    unsigned long long d;
    asm("fma.rn.f32x2 %0, %1, %2, %3;" : "=l"(d) : "l"(a), "l"(b), "l"(c));
    return d;
}
__device__ __forceinline__ unsigned long long dup2(float x) {
    unsigned long long d;
    asm("mov.b64 %0, {%1, %1};" : "=l"(d) : "f"(x));
    return d;
}
__device__ __forceinline__ void unpack2(unsigned long long v, float& lo, float& hi) {
    asm("mov.b64 {%0, %1}, %2;" : "=f"(lo), "=f"(hi) : "l"(v));
}
__device__ __forceinline__ void cp16(uint32_t dst, const void* src) {
    asm volatile("cp.async.cg.shared.global [%0], [%1], 16;" :: "r"(dst), "l"(src));
}
__device__ __forceinline__ void gbar(int id) {
    asm volatile("bar.sync %0, %1;" :: "r"(id), "r"(GSZ) : "memory");
}

__global__ void __launch_bounds__(TPB, 1)
onehot_argmax_kernel(const float* __restrict__ x,
                     const float* __restrict__ W,
                     const float* __restrict__ b,
                     float* __restrict__ out,
                     int ntiles) {
    extern __shared__ float smem[];
    float* Ws = smem;                 // [64][64] k-major
    float* bs = Ws + 4096;            // [64]
    float* xs = bs + 64;              // 8 x 4096 floats, swizzled tiles

    const int t  = threadIdx.x;
    const int p  = t / GSZ;           // group 0..3
    const int tl = t & (GSZ - 1);     // index within group
    const int g  = tl >> 4;           // row group 0..7, rows 8g..8g+7
    const int a  = tl & 15;           // column selector: cols 4a..4a+3
    const int nstreams = NG * gridDim.x;
    const int s0 = blockIdx.x * NG + p;   // this group's stream id

    const uint32_t s_ws = (uint32_t)__cvta_generic_to_shared(Ws);
    const uint32_t s_bs = (uint32_t)__cvta_generic_to_shared(bs);
    const uint32_t s_xs = (uint32_t)__cvta_generic_to_shared(xs);

    // ---- prologue: whole block stages W+b; each group stages its tile0 ----
    {
        const float4* W4 = (const float4*)W;
        cp16(s_ws + t * 16, W4 + t);
        cp16(s_ws + (t + TPB) * 16, W4 + t + TPB);
        if (t < 16) cp16(s_bs + t * 16, ((const float4*)b) + t);

        if (s0 < ntiles) {
            const float4* xg = (const float4*)x + (long long)s0 * TILE_F4;
            const uint32_t s_dst = s_xs + (uint32_t)(p * 2) * (TILE_FLOATS * 4u);
#pragma unroll
            for (int it = 0; it < 8; it++) {
                int f = tl + it * GSZ;            // 0..1023
                int row = f >> 4, q = f & 15;
                int off = row * 64 + ((4 * q) ^ (row & 0x1C));
                cp16(s_dst + off * 4, xg + f);
            }
        }
        asm volatile("cp.async.commit_group;" ::: "memory");
    }
    __syncthreads();   // W/b visible to everyone; groups diverge from here

    const int swb = (g & 3) << 3;
    int buf = 0;

    for (int tile = s0; tile < ntiles; tile += nstreams) {
        asm volatile("cp.async.wait_group 0;" ::: "memory");
        gbar(1 + p);   // buf data visible to whole group; prior reads done

        // ---- prefetch next tile into buf^1 (overlaps compute below) ----
        {
            int nt = tile + nstreams;
            if (nt >= ntiles) nt = tile;          // harmless duplicate
            const float4* xg = (const float4*)x + (long long)nt * TILE_F4;
            const uint32_t s_dst = s_xs +
                (uint32_t)(p * 2 + (buf ^ 1)) * (TILE_FLOATS * 4u);
#pragma unroll
            for (int it = 0; it < 8; it++) {
                int f = tl + it * GSZ;
                int row = f >> 4, q = f & 15;
                int off = row * 64 + ((4 * q) ^ (row & 0x1C));
                cp16(s_dst + off * 4, xg + f);
            }
            asm volatile("cp.async.commit_group;" ::: "memory");
        }

        // ---- init acc with b (cols 4a..4a+3) ----
        unsigned long long acc[8][2];
        {
            ulonglong2 b0 = *(const ulonglong2*)(bs + 4 * a);
#pragma unroll
            for (int i = 0; i < 8; i++) { acc[i][0] = b0.x; acc[i][1] = b0.y; }
        }

        const float* xbase = xs + (p * 2 + buf) * TILE_FLOATS + (g << 9);

        // ---- mainloop: 16 k-quads, 64 k total ----
#pragma unroll 2
        for (int kq = 0; kq < 16; kq++) {
            const int e0 = (4 * kq) ^ swb;
            const int e4 = (4 * kq) ^ (swb + 4);
            float4 xr[8];
#pragma unroll
            for (int i = 0; i < 8; i++)
                xr[i] = *(const float4*)(xbase + (i << 6) + ((i & 4) ? e4 : e0));
#pragma unroll
            for (int dk = 0; dk < 4; dk++) {
                const int k = 4 * kq + dk;
                ulonglong2 w0 = *(const ulonglong2*)(Ws + (k << 6) + 4 * a);
#pragma unroll
                for (int i = 0; i < 8; i++) {
                    float xk = (dk == 0) ? xr[i].x : (dk == 1) ? xr[i].y
                             : (dk == 2) ? xr[i].z : xr[i].w;
                    unsigned long long x2 = dup2(xk);
                    acc[i][0] = fma2(x2, w0.x, acc[i][0]);
                    acc[i][1] = fma2(x2, w0.y, acc[i][1]);
                }
            }
        }

        // ---- per-thread argmax over its 4 cols (ascending j, strict >) ----
        float bv[8];
        int bj[8];
#pragma unroll
        for (int i = 0; i < 8; i++) { bv[i] = __int_as_float(0xff800000); bj[i] = 0; }
#pragma unroll
        for (int c = 0; c < 2; c++) {
            const int j0 = 4 * a + 2 * c;
#pragma unroll
            for (int i = 0; i < 8; i++) {
                float lo, hi;
                unpack2(acc[i][c], lo, hi);
                if (lo > bv[i]) { bv[i] = lo; bj[i] = j0; }
                if (hi > bv[i]) { bv[i] = hi; bj[i] = j0 + 1; }
            }
        }

        // ---- reduce across the 16 column-lanes (first-max tie-break);
        //      offsets 1,2,4,8 stay within the 16-lane a-dimension ----
#pragma unroll
        for (int off = 1; off <= 8; off <<= 1) {
#pragma unroll
            for (int i = 0; i < 8; i++) {
                float pv = __shfl_xor_sync(0xffffffffu, bv[i], off);
                int   pj = __shfl_xor_sync(0xffffffffu, bj[i], off);
                if (pv > bv[i] || (pv == bv[i] && pj < bj[i])) { bv[i] = pv; bj[i] = pj; }
            }
        }

        // ---- store own rows: per row i, lane a writes float4 q=a ----
        {
            float4* og = (float4*)out + (long long)tile * TILE_F4 + (g << 7);
#pragma unroll
            for (int i = 0; i < 8; i++) {
                const int lab = bj[i];
                float4 v;
                v.x = (4 * a + 0 == lab) ? 1.0f : 0.0f;
                v.y = (4 * a + 1 == lab) ? 1.0f : 0.0f;
                v.z = (4 * a + 2 == lab) ? 1.0f : 0.0f;
                v.w = (4 * a + 3 == lab) ? 1.0f : 0.0f;
                og[(i << 4) + a] = v;
            }
        }

        buf ^= 1;
    }
}

extern "C" void kernel_launch(void* const* d_in, const int* in_sizes, int n_in,
                              void* d_out, int out_size) {
    const float* x = (const float*)d_in[0];
    const float* W = (const float*)d_in[1];
    const float* b = (const float*)d_in[2];
    float* out = (float*)d_out;

    const long long rows = (long long)in_sizes[0] / DIMS;   // 2097152
    const int ntiles = (int)(rows / TROWS);                  // 32768

    int sms = 148;
    cudaDeviceGetAttribute(&sms, cudaDevAttrMultiProcessorCount, 0);

    cudaFuncSetAttribute(onehot_argmax_kernel,
                         cudaFuncAttributeMaxDynamicSharedMemorySize, SMEM_BYTES);
    onehot_argmax_kernel<<<sms, TPB, SMEM_BYTES>>>(x, W, b, out, ntiles);
}